// round 7
// baseline (speedup 1.0000x reference)
#include <cuda_runtime.h>
#include <cstdint>

// Problem constants
#define MROWS   32768
#define DIM     768
#define VPOS    10240
#define POS_OFF ((size_t)VPOS * DIM)

// GEMM tiling: CTA 128x256, 8 warps (2m x 4n), warp tile 64x64
#define BM 128
#define BN 256
#define BK 32
#define STRIDE 36                   // smem row stride in floats (padded)
#define A_ROWS BM
#define B_ROWS BN
#define ASZ (A_ROWS * STRIDE)       // 4608 floats
#define BSZ (B_ROWS * STRIDE)       // 9216 floats
#define STAGE_F (ASZ + BSZ)         // 13824 floats
#define SMEM_BYTES (2 * STAGE_F * 4)  // 110592 bytes, double buffered
#define NKT (DIM / BK)              // 24

// Output layout (flattened concat of the reference tuple, as float32)
#define OUT_Y     ((size_t)MROWS * DIM)
#define OUT_PID   ((size_t)MROWS * 2)
#define OUT_TOTAL (OUT_Y + OUT_PID + (size_t)MROWS)

// Device scratch
__device__ float g_Xp[(size_t)MROWS * DIM];  // tf32-rounded x (96 MB)
__device__ float g_Wp[DIM * DIM];   // permuted, x2, tf32-rounded weights [d][j]
__device__ float g_bias[DIM];       // -sum_k W[d,k]
__device__ int g_pid0[MROWS];
__device__ int g_pid1[MROWS];
__device__ int g_rawc0[MROWS];
__device__ int g_rawc1[MROWS];
__device__ unsigned char g_ok[MROWS];
__device__ int g_coord_fmt;
__device__ int g_valid_fmt;

__device__ __forceinline__ uint32_t f2tf(float f) {
    uint32_t u;
    asm("cvt.rna.tf32.f32 %0, %1;" : "=r"(u) : "f"(f));
    return u;
}

__device__ __forceinline__ void cp_async16(uint32_t s, const void* g) {
    asm volatile("cp.async.cg.shared.global [%0], [%1], 16;\n" :: "r"(s), "l"(g));
}

__device__ __forceinline__ void mma_tf32(float* c, const uint32_t* a, const uint32_t* b) {
    asm volatile(
        "mma.sync.aligned.m16n8k8.row.col.f32.tf32.tf32.f32 "
        "{%0,%1,%2,%3}, {%4,%5,%6,%7}, {%8,%9}, {%0,%1,%2,%3};\n"
        : "+f"(c[0]), "+f"(c[1]), "+f"(c[2]), "+f"(c[3])
        : "r"(a[0]), "r"(a[1]), "r"(a[2]), "r"(a[3]), "r"(b[0]), "r"(b[1]));
}

// ---------------------------------------------------------------------------
// dtype detection for patch_coord / patch_valid (values in [0,64), 0/1)
// ---------------------------------------------------------------------------
__global__ void detect_kernel(const void* coordp, const void* validp) {
    __shared__ unsigned int s_or_all, s_or_odd, s_vb_or, s_vb_gt1;
    int tid = threadIdx.x;
    if (tid == 0) { s_or_all = 0; s_or_odd = 0; s_vb_or = 0; s_vb_gt1 = 0; }
    __syncthreads();

    const unsigned int* cw = (const unsigned int*)coordp;
    unsigned int oa = 0, oo = 0;
    for (int i = tid; i < 2048; i += 256) {
        unsigned int w = cw[i];
        oa |= w;
        if (i & 1) oo |= w;
    }
    atomicOr(&s_or_all, oa);
    atomicOr(&s_or_odd, oo);

    const unsigned char* vb = (const unsigned char*)validp;
    unsigned int vo = 0, vg = 0;
    for (int i = tid; i < 4096; i += 256) {
        unsigned char b = vb[i];
        if (i & 3) vo |= b;
        if (b > 1) vg = 1;
    }
    atomicOr(&s_vb_or, vo);
    atomicOr(&s_vb_gt1, vg);
    __syncthreads();

    if (tid == 0) {
        g_coord_fmt = (s_or_all >= 0x10000u) ? 2 : (s_or_odd == 0 ? 1 : 0);
        g_valid_fmt = s_vb_gt1 ? 2 : (s_vb_or == 0 ? 0 : 1);
    }
}

__global__ void norm_kernel(const void* coordp, const void* validp) {
    int i = blockIdx.x * blockDim.x + threadIdx.x;
    if (i >= MROWS) return;
    int cf = g_coord_fmt;
    int c0, c1;
    if (cf == 1) {
        const long long* c = (const long long*)coordp;
        c0 = (int)c[2LL * i]; c1 = (int)c[2LL * i + 1];
    } else if (cf == 2) {
        const float* c = (const float*)coordp;
        c0 = (int)c[2LL * i]; c1 = (int)c[2LL * i + 1];
    } else {
        const int* c = (const int*)coordp;
        c0 = c[2 * i]; c1 = c[2 * i + 1];
    }
    g_rawc0[i] = c0;
    g_rawc1[i] = c1;
    g_pid0[i] = c1 > 0 ? c1 : 0;
    g_pid1[i] = c0 > 0 ? c0 : 0;

    int vf = g_valid_fmt;
    bool v;
    if (vf == 0)      v = ((const int*)validp)[i] != 0;
    else if (vf == 2) v = ((const float*)validp)[i] != 0.0f;
    else              v = ((const unsigned char*)validp)[i] != 0;
    g_ok[i] = v ? 1 : 0;
}

// ---------------------------------------------------------------------------
// Pre-round x to tf32 (RNA) once: removes all cvt from the GEMM inner loop.
// ---------------------------------------------------------------------------
__global__ void __launch_bounds__(256) xprep_kernel(const float* __restrict__ x) {
    size_t i = ((size_t)blockIdx.x * 256 + threadIdx.x) * 4;
    float4 v = *reinterpret_cast<const float4*>(x + i);
    uint4 o;
    o.x = f2tf(v.x); o.y = f2tf(v.y); o.z = f2tf(v.z); o.w = f2tf(v.w);
    *reinterpret_cast<uint4*>(&g_Xp[i]) = o;
}

// ---------------------------------------------------------------------------
// W'[d][j] = tf32(2*W[d][k(j)]), bias[d] = -sum_k W[d][k]
// j = ph*48 + pw*3 + c -> k = c*256 + ph*16 + pw
// ---------------------------------------------------------------------------
__global__ void prep_kernel(const float* __restrict__ W) {
    int d = blockIdx.x;
    const float* wrow = W + (size_t)d * DIM;
    __shared__ float red[256];
    float s = 0.f;
    for (int j = threadIdx.x; j < DIM; j += 256) {
        int c = j % 3;
        int t = j / 3;
        int pw = t & 15;
        int ph = t >> 4;
        int k = c * 256 + ph * 16 + pw;
        float w = wrow[k];
        s += w;
        g_Wp[(size_t)d * DIM + j] = __uint_as_float(f2tf(2.0f * w));
    }
    red[threadIdx.x] = s;
    __syncthreads();
    for (int off = 128; off > 0; off >>= 1) {
        if (threadIdx.x < off) red[threadIdx.x] += red[threadIdx.x + off];
        __syncthreads();
    }
    if (threadIdx.x == 0) g_bias[d] = -red[0];
}

// ---------------------------------------------------------------------------
// Main fused GEMM: y = Xp @ Wp^T + bias + pos(gather), tf32 warp MMA
// grid (768/BN=3, 32768/BM=256), 256 threads, double-buffered smem
// Warp layout: wm = warp>>2 (2 along M, 64 rows), wn = warp&3 (4 along N, 64 cols)
// ---------------------------------------------------------------------------
__global__ void __launch_bounds__(256, 1)
gemm_kernel(const float* __restrict__ pos_table,
            float* __restrict__ out) {
    extern __shared__ float smem[];

    const int lane = threadIdx.x & 31;
    const int warp = threadIdx.x >> 5;
    const int wm = warp >> 2;   // 0..1  (64 rows each)
    const int wn = warp & 3;    // 0..3  (64 cols each)

    float acc[4][8][4];
    #pragma unroll
    for (int a = 0; a < 4; a++)
        #pragma unroll
        for (int b = 0; b < 8; b++)
            #pragma unroll
            for (int c = 0; c < 4; c++) acc[a][b][c] = 0.f;

    const float* Abase = g_Xp + (size_t)(blockIdx.y * BM) * DIM;
    const float* Bbase = g_Wp + (size_t)(blockIdx.x * BN) * DIM;

    // async load of tile kt into stage: A = 1024 x 16B, B = 2048 x 16B
    auto issue = [&](int kt, int stage) {
        float* As = smem + stage * STAGE_F;
        float* Bs = As + ASZ;
        const float* Ag = Abase + kt * BK;
        const float* Bg = Bbase + kt * BK;
        #pragma unroll
        for (int i = 0; i < 12; i++) {
            int linear = threadIdx.x + i * 256;   // 0..3071
            if (linear < 1024) {
                int row = linear >> 3;
                int col4 = (linear & 7) * 4;
                uint32_t sa = (uint32_t)__cvta_generic_to_shared(&As[row * STRIDE + col4]);
                cp_async16(sa, Ag + (size_t)row * DIM + col4);
            } else {
                int l = linear - 1024;
                int row = l >> 3;
                int col4 = (l & 7) * 4;
                uint32_t sbp = (uint32_t)__cvta_generic_to_shared(&Bs[row * STRIDE + col4]);
                cp_async16(sbp, Bg + (size_t)row * DIM + col4);
            }
        }
        asm volatile("cp.async.commit_group;\n");
    };

    issue(0, 0);

    for (int kt = 0; kt < NKT; kt++) {
        int stage = kt & 1;
        if (kt + 1 < NKT) {
            issue(kt + 1, stage ^ 1);
            asm volatile("cp.async.wait_group 1;\n");
        } else {
            asm volatile("cp.async.wait_group 0;\n");
        }
        __syncthreads();

        const float* As = smem + stage * STAGE_F;
        const float* Bs = As + ASZ;

        #pragma unroll
        for (int ks = 0; ks < 4; ks++) {
            uint32_t af[4][4], bf[8][2];
            const int cka = ks * 8 + (lane & 3);
            #pragma unroll
            for (int im = 0; im < 4; im++) {
                int r0 = wm * 64 + im * 16 + (lane >> 2);
                af[im][0] = __float_as_uint(As[r0 * STRIDE + cka]);
                af[im][1] = __float_as_uint(As[(r0 + 8) * STRIDE + cka]);
                af[im][2] = __float_as_uint(As[r0 * STRIDE + cka + 4]);
                af[im][3] = __float_as_uint(As[(r0 + 8) * STRIDE + cka + 4]);
            }
            #pragma unroll
            for (int in = 0; in < 8; in++) {
                int n0 = wn * 64 + in * 8 + (lane >> 2);
                bf[in][0] = __float_as_uint(Bs[n0 * STRIDE + cka]);
                bf[in][1] = __float_as_uint(Bs[n0 * STRIDE + cka + 4]);
            }
            #pragma unroll
            for (int im = 0; im < 4; im++)
                #pragma unroll
                for (int in = 0; in < 8; in++)
                    mma_tf32(acc[im][in], af[im], bf[in]);
        }
        __syncthreads();
    }

    // Epilogue: + bias + pos gather (normalized indices), write float2
    const int gm0 = blockIdx.y * BM + wm * 64;
    const int gn0 = blockIdx.x * BN + wn * 64;

    #pragma unroll
    for (int im = 0; im < 4; im++) {
        int rbase = gm0 + im * 16 + (lane >> 2);
        #pragma unroll
        for (int half = 0; half < 2; half++) {
            int r = rbase + half * 8;
            int p0 = g_pid0[r];
            int p1 = g_pid1[r];
            bool v = (g_ok[r] != 0);
            const float* t0 = pos_table + (size_t)p0 * DIM;
            const float* t1 = pos_table + POS_OFF + (size_t)p1 * DIM;
            float* orow = out + (size_t)r * DIM;
            #pragma unroll
            for (int in = 0; in < 8; in++) {
                int d = gn0 + in * 8 + (lane & 3) * 2;
                float v0 = acc[im][in][half * 2 + 0] + g_bias[d];
                float v1 = acc[im][in][half * 2 + 1] + g_bias[d + 1];
                if (v) {
                    v0 += t0[d] + t1[d];
                    v1 += t0[d + 1] + t1[d + 1];
                }
                float2 o; o.x = v0; o.y = v1;
                *reinterpret_cast<float2*>(&orow[d]) = o;
            }
        }
    }
}

// ---------------------------------------------------------------------------
// Aux outputs: position_ids (reversed raw coords) + padding mask, as float32
// ---------------------------------------------------------------------------
__global__ void aux_kernel(float* __restrict__ out_pid,
                           float* __restrict__ out_pad) {
    int i = blockIdx.x * blockDim.x + threadIdx.x;
    if (i < MROWS) {
        out_pid[2LL * i]     = (float)g_rawc1[i];
        out_pid[2LL * i + 1] = (float)g_rawc0[i];
        out_pad[i] = g_ok[i] ? 0.0f : 1.0f;
    }
}

extern "C" void kernel_launch(void* const* d_in, const int* in_sizes, int n_in,
                              void* d_out, int out_size) {
    const float* x     = (const float*)d_in[0];
    const void*  coord = d_in[1];
    const void*  valid = d_in[2];
    const float* W     = (const float*)d_in[3];
    const float* pos   = (const float*)d_in[4];
    float* out = (float*)d_out;

    cudaFuncSetAttribute(gemm_kernel,
                         cudaFuncAttributeMaxDynamicSharedMemorySize, SMEM_BYTES);

    detect_kernel<<<1, 256>>>(coord, valid);
    norm_kernel<<<(MROWS + 255) / 256, 256>>>(coord, valid);
    xprep_kernel<<<(int)(((size_t)MROWS * DIM) / 4 / 256), 256>>>(x);
    prep_kernel<<<DIM, 256>>>(W);

    dim3 grid(DIM / BN, MROWS / BM);   // (3, 256)
    gemm_kernel<<<grid, 256, SMEM_BYTES>>>(pos, out);

    if ((size_t)out_size >= OUT_TOTAL) {
        aux_kernel<<<(MROWS + 255) / 256, 256>>>(
            out + OUT_Y, out + OUT_Y + OUT_PID);
    }
}

// round 10
// speedup vs baseline: 1.0957x; 1.0957x over previous
#include <cuda_runtime.h>
#include <cstdint>

// Problem constants
#define MROWS   32768
#define DIM     768
#define VPOS    10240
#define POS_OFF ((size_t)VPOS * DIM)

// GEMM tiling: CTA 128x128, 8 warps (2m x 4n), warp tile 64x32, 3-stage pipeline
#define BM 128
#define BN 128
#define BK 32
#define STRIDE 36                   // smem row stride in floats (padded)
#define ASZ (BM * STRIDE)           // 4608 floats
#define STAGE_F (2 * ASZ)           // A + B per stage = 9216 floats
#define NSTAGE 3
#define SMEM_BYTES (NSTAGE * STAGE_F * 4)   // 110592 bytes
#define NKT (DIM / BK)              // 24

// Output layout (flattened concat of the reference tuple, as float32)
#define OUT_Y     ((size_t)MROWS * DIM)
#define OUT_PID   ((size_t)MROWS * 2)
#define OUT_TOTAL (OUT_Y + OUT_PID + (size_t)MROWS)

// Device scratch
__device__ float g_Wp[DIM * DIM];   // permuted, x2, tf32-rounded weights [d][j]
__device__ float g_bias[DIM];       // -sum_k W[d,k]
__device__ int g_pid0[MROWS];
__device__ int g_pid1[MROWS];
__device__ int g_rawc0[MROWS];
__device__ int g_rawc1[MROWS];
__device__ unsigned char g_ok[MROWS];
__device__ int g_coord_fmt;
__device__ int g_valid_fmt;

__device__ __forceinline__ uint32_t f2tf(float f) {
    uint32_t u;
    asm("cvt.rna.tf32.f32 %0, %1;" : "=r"(u) : "f"(f));
    return u;
}

__device__ __forceinline__ void cp_async16(uint32_t s, const void* g) {
    asm volatile("cp.async.cg.shared.global [%0], [%1], 16;\n" :: "r"(s), "l"(g));
}

__device__ __forceinline__ void mma_tf32(float* c, const uint32_t* a, const uint32_t* b) {
    asm volatile(
        "mma.sync.aligned.m16n8k8.row.col.f32.tf32.tf32.f32 "
        "{%0,%1,%2,%3}, {%4,%5,%6,%7}, {%8,%9}, {%0,%1,%2,%3};\n"
        : "+f"(c[0]), "+f"(c[1]), "+f"(c[2]), "+f"(c[3])
        : "r"(a[0]), "r"(a[1]), "r"(a[2]), "r"(a[3]), "r"(b[0]), "r"(b[1]));
}

// ---------------------------------------------------------------------------
// dtype detection for patch_coord / patch_valid (values in [0,64), 0/1)
// ---------------------------------------------------------------------------
__global__ void detect_kernel(const void* coordp, const void* validp) {
    __shared__ unsigned int s_or_all, s_or_odd, s_vb_or, s_vb_gt1;
    int tid = threadIdx.x;
    if (tid == 0) { s_or_all = 0; s_or_odd = 0; s_vb_or = 0; s_vb_gt1 = 0; }
    __syncthreads();

    const unsigned int* cw = (const unsigned int*)coordp;
    unsigned int oa = 0, oo = 0;
    for (int i = tid; i < 2048; i += 256) {
        unsigned int w = cw[i];
        oa |= w;
        if (i & 1) oo |= w;
    }
    atomicOr(&s_or_all, oa);
    atomicOr(&s_or_odd, oo);

    const unsigned char* vb = (const unsigned char*)validp;
    unsigned int vo = 0, vg = 0;
    for (int i = tid; i < 4096; i += 256) {
        unsigned char b = vb[i];
        if (i & 3) vo |= b;
        if (b > 1) vg = 1;
    }
    atomicOr(&s_vb_or, vo);
    atomicOr(&s_vb_gt1, vg);
    __syncthreads();

    if (tid == 0) {
        g_coord_fmt = (s_or_all >= 0x10000u) ? 2 : (s_or_odd == 0 ? 1 : 0);
        g_valid_fmt = s_vb_gt1 ? 2 : (s_vb_or == 0 ? 0 : 1);
    }
}

__global__ void norm_kernel(const void* coordp, const void* validp) {
    int i = blockIdx.x * blockDim.x + threadIdx.x;
    if (i >= MROWS) return;
    int cf = g_coord_fmt;
    int c0, c1;
    if (cf == 1) {
        const long long* c = (const long long*)coordp;
        c0 = (int)c[2LL * i]; c1 = (int)c[2LL * i + 1];
    } else if (cf == 2) {
        const float* c = (const float*)coordp;
        c0 = (int)c[2LL * i]; c1 = (int)c[2LL * i + 1];
    } else {
        const int* c = (const int*)coordp;
        c0 = c[2 * i]; c1 = c[2 * i + 1];
    }
    g_rawc0[i] = c0;
    g_rawc1[i] = c1;
    g_pid0[i] = c1 > 0 ? c1 : 0;
    g_pid1[i] = c0 > 0 ? c0 : 0;

    int vf = g_valid_fmt;
    bool v;
    if (vf == 0)      v = ((const int*)validp)[i] != 0;
    else if (vf == 2) v = ((const float*)validp)[i] != 0.0f;
    else              v = ((const unsigned char*)validp)[i] != 0;
    g_ok[i] = v ? 1 : 0;
}

// ---------------------------------------------------------------------------
// W'[d][j] = tf32(2*W[d][k(j)]), bias[d] = -sum_k W[d][k]
// j = ph*48 + pw*3 + c -> k = c*256 + ph*16 + pw
// ---------------------------------------------------------------------------
__global__ void prep_kernel(const float* __restrict__ W) {
    int d = blockIdx.x;
    const float* wrow = W + (size_t)d * DIM;
    __shared__ float red[256];
    float s = 0.f;
    for (int j = threadIdx.x; j < DIM; j += 256) {
        int c = j % 3;
        int t = j / 3;
        int pw = t & 15;
        int ph = t >> 4;
        int k = c * 256 + ph * 16 + pw;
        float w = wrow[k];
        s += w;
        g_Wp[(size_t)d * DIM + j] = __uint_as_float(f2tf(2.0f * w));
    }
    red[threadIdx.x] = s;
    __syncthreads();
    for (int off = 128; off > 0; off >>= 1) {
        if (threadIdx.x < off) red[threadIdx.x] += red[threadIdx.x + off];
        __syncthreads();
    }
    if (threadIdx.x == 0) g_bias[d] = -red[0];
}

// ---------------------------------------------------------------------------
// Main fused GEMM: y = x @ Wp^T + bias + pos(gather), tf32 warp MMA
// grid (768/BN=6, 32768/BM=256), 256 threads, 3-stage cp.async pipeline,
// one __syncthreads per k-tile, register double-buffered fragments.
// ---------------------------------------------------------------------------
__global__ void __launch_bounds__(256, 2)
gemm_kernel(const float* __restrict__ x,
            const float* __restrict__ pos_table,
            float* __restrict__ out) {
    extern __shared__ float smem[];

    const int lane = threadIdx.x & 31;
    const int warp = threadIdx.x >> 5;
    const int wm = warp & 1;   // 0..1  (m, 64 rows each)
    const int wn = warp >> 1;  // 0..3  (n, 32 cols each)

    float acc[4][4][4];
    #pragma unroll
    for (int a = 0; a < 4; a++)
        #pragma unroll
        for (int b = 0; b < 4; b++)
            #pragma unroll
            for (int c = 0; c < 4; c++) acc[a][b][c] = 0.f;

    const float* Abase = x + (size_t)(blockIdx.y * BM) * DIM;
    const float* Bbase = g_Wp + (size_t)(blockIdx.x * BN) * DIM;

    // async load of tile kt into stage slot
    auto issue = [&](int kt, int slot) {
        float* As = smem + slot * STAGE_F;
        float* Bs = As + ASZ;
        const float* Ag = Abase + kt * BK;
        const float* Bg = Bbase + kt * BK;
        #pragma unroll
        for (int i = 0; i < 4; i++) {
            int linear = threadIdx.x + i * 256;
            int row = linear >> 3;
            int col4 = (linear & 7) * 4;
            uint32_t sa = (uint32_t)__cvta_generic_to_shared(&As[row * STRIDE + col4]);
            cp_async16(sa, Ag + (size_t)row * DIM + col4);
            uint32_t sbp = (uint32_t)__cvta_generic_to_shared(&Bs[row * STRIDE + col4]);
            cp_async16(sbp, Bg + (size_t)row * DIM + col4);
        }
        asm volatile("cp.async.commit_group;\n");
    };

    issue(0, 0);
    issue(1, 1);

    // Prefetch epilogue row metadata (hides gmem latency behind mainloop)
    int ep_p0[8], ep_p1[8];
    unsigned char ep_ok[8];
    {
        const int gm0 = blockIdx.y * BM + wm * 64;
        #pragma unroll
        for (int im = 0; im < 4; im++) {
            #pragma unroll
            for (int half = 0; half < 2; half++) {
                int r = gm0 + im * 16 + (lane >> 2) + half * 8;
                ep_p0[im * 2 + half] = g_pid0[r];
                ep_p1[im * 2 + half] = g_pid1[r];
                ep_ok[im * 2 + half] = g_ok[r];
            }
        }
    }

    for (int kt = 0; kt < NKT; kt++) {
        const int slot = kt % NSTAGE;
        if (kt + 1 < NKT) {
            asm volatile("cp.async.wait_group 1;\n");
        } else {
            asm volatile("cp.async.wait_group 0;\n");
        }
        __syncthreads();           // single barrier per tile: data visible + prior readers done
        if (kt + 2 < NKT) issue(kt + 2, (kt + 2) % NSTAGE);

        const float* As = smem + slot * STAGE_F;
        const float* Bs = As + ASZ;

        // fragment loaders
        uint32_t af[2][4][4], bf[2][4][2];
        auto load_frags = [&](int ks, int buf) {
            const int cka = ks * 8 + (lane & 3);
            #pragma unroll
            for (int im = 0; im < 4; im++) {
                int r0 = wm * 64 + im * 16 + (lane >> 2);
                af[buf][im][0] = f2tf(As[r0 * STRIDE + cka]);
                af[buf][im][1] = f2tf(As[(r0 + 8) * STRIDE + cka]);
                af[buf][im][2] = f2tf(As[r0 * STRIDE + cka + 4]);
                af[buf][im][3] = f2tf(As[(r0 + 8) * STRIDE + cka + 4]);
            }
            #pragma unroll
            for (int in = 0; in < 4; in++) {
                int n0 = wn * 32 + in * 8 + (lane >> 2);
                bf[buf][in][0] = __float_as_uint(Bs[n0 * STRIDE + cka]);     // pre-rounded
                bf[buf][in][1] = __float_as_uint(Bs[n0 * STRIDE + cka + 4]);
            }
        };

        load_frags(0, 0);
        #pragma unroll
        for (int ks = 0; ks < 4; ks++) {
            const int cur = ks & 1;
            if (ks < 3) load_frags(ks + 1, cur ^ 1);
            #pragma unroll
            for (int im = 0; im < 4; im++)
                #pragma unroll
                for (int in = 0; in < 4; in++)
                    mma_tf32(acc[im][in], af[cur][im], bf[cur][in]);
        }
    }

    // Epilogue: + bias + pos gather, write float2
    const int gm0 = blockIdx.y * BM + wm * 64;
    const int gn0 = blockIdx.x * BN + wn * 32;

    #pragma unroll
    for (int im = 0; im < 4; im++) {
        int rbase = gm0 + im * 16 + (lane >> 2);
        #pragma unroll
        for (int half = 0; half < 2; half++) {
            int r = rbase + half * 8;
            int p0 = ep_p0[im * 2 + half];
            int p1 = ep_p1[im * 2 + half];
            bool v = (ep_ok[im * 2 + half] != 0);
            const float* t0 = pos_table + (size_t)p0 * DIM;
            const float* t1 = pos_table + POS_OFF + (size_t)p1 * DIM;
            float* orow = out + (size_t)r * DIM;
            #pragma unroll
            for (int in = 0; in < 4; in++) {
                int d = gn0 + in * 8 + (lane & 3) * 2;
                float v0 = acc[im][in][half * 2 + 0] + g_bias[d];
                float v1 = acc[im][in][half * 2 + 1] + g_bias[d + 1];
                if (v) {
                    v0 += t0[d] + t1[d];
                    v1 += t0[d + 1] + t1[d + 1];
                }
                float2 o; o.x = v0; o.y = v1;
                *reinterpret_cast<float2*>(&orow[d]) = o;
            }
        }
    }
}

// ---------------------------------------------------------------------------
// Aux outputs: position_ids (reversed raw coords) + padding mask, as float32
// ---------------------------------------------------------------------------
__global__ void aux_kernel(float* __restrict__ out_pid,
                           float* __restrict__ out_pad) {
    int i = blockIdx.x * blockDim.x + threadIdx.x;
    if (i < MROWS) {
        out_pid[2LL * i]     = (float)g_rawc1[i];
        out_pid[2LL * i + 1] = (float)g_rawc0[i];
        out_pad[i] = g_ok[i] ? 0.0f : 1.0f;
    }
}

extern "C" void kernel_launch(void* const* d_in, const int* in_sizes, int n_in,
                              void* d_out, int out_size) {
    const float* x     = (const float*)d_in[0];
    const void*  coord = d_in[1];
    const void*  valid = d_in[2];
    const float* W     = (const float*)d_in[3];
    const float* pos   = (const float*)d_in[4];
    float* out = (float*)d_out;

    cudaFuncSetAttribute(gemm_kernel,
                         cudaFuncAttributeMaxDynamicSharedMemorySize, SMEM_BYTES);

    detect_kernel<<<1, 256>>>(coord, valid);
    norm_kernel<<<(MROWS + 255) / 256, 256>>>(coord, valid);
    prep_kernel<<<DIM, 256>>>(W);

    dim3 grid(DIM / BN, MROWS / BM);   // (6, 256)
    gemm_kernel<<<grid, 256, SMEM_BYTES>>>(x, pos, out);

    if ((size_t)out_size >= OUT_TOTAL) {
        aux_kernel<<<(MROWS + 255) / 256, 256>>>(
            out + OUT_Y, out + OUT_Y + OUT_PID);
    }
}

// round 11
// speedup vs baseline: 1.1394x; 1.0399x over previous
#include <cuda_runtime.h>
#include <cstdint>

// Problem constants
#define MROWS   32768
#define DIM     768
#define VPOS    10240
#define POS_OFF ((size_t)VPOS * DIM)

// GEMM tiling: CTA 128x128, 8 warps (2m x 4n), warp tile 64x32, 2-stage pipeline
// smem layout per stage: A 128 rows x 32 floats (no pad), B 128 x 32.
// K is pre-permuted in gmem within 16-groups (k' = 4*(k%4) + (k%16)/4) so one
// LDS.128 per lane yields both k8 fragment halves of a k16 group.
#define BM 128
#define BN 128
#define BK 32
#define ASZ (BM * 32)               // 4096 floats
#define STAGE_F (2 * ASZ)           // 8192 floats (32KB)
#define SMEM_BYTES (2 * STAGE_F * 4)  // 65536 bytes, double buffered
#define NKT (DIM / BK)              // 24

// Output layout (flattened concat of the reference tuple, as float32)
#define OUT_Y     ((size_t)MROWS * DIM)
#define OUT_PID   ((size_t)MROWS * 2)
#define OUT_TOTAL (OUT_Y + OUT_PID + (size_t)MROWS)

// Device scratch
__device__ float g_Xp[(size_t)MROWS * DIM];  // tf32-rounded, k-permuted x
__device__ float g_Wp[DIM * DIM];   // patch-permuted, x2, tf32-rounded, k-permuted W
__device__ float g_bias[DIM];       // -sum_k W[d,k]
__device__ int g_pid0[MROWS];
__device__ int g_pid1[MROWS];
__device__ int g_rawc0[MROWS];
__device__ int g_rawc1[MROWS];
__device__ unsigned char g_ok[MROWS];
__device__ int g_coord_fmt;
__device__ int g_valid_fmt;

__device__ __forceinline__ uint32_t f2tf(float f) {
    uint32_t u;
    asm("cvt.rna.tf32.f32 %0, %1;" : "=r"(u) : "f"(f));
    return u;
}

__device__ __forceinline__ void cp_async16(uint32_t s, const void* g) {
    asm volatile("cp.async.cg.shared.global [%0], [%1], 16;\n" :: "r"(s), "l"(g));
}

__device__ __forceinline__ void mma_tf32(float* c,
                                         uint32_t a0, uint32_t a1, uint32_t a2, uint32_t a3,
                                         uint32_t b0, uint32_t b1) {
    asm volatile(
        "mma.sync.aligned.m16n8k8.row.col.f32.tf32.tf32.f32 "
        "{%0,%1,%2,%3}, {%4,%5,%6,%7}, {%8,%9}, {%0,%1,%2,%3};\n"
        : "+f"(c[0]), "+f"(c[1]), "+f"(c[2]), "+f"(c[3])
        : "r"(a0), "r"(a1), "r"(a2), "r"(a3), "r"(b0), "r"(b1));
}

// ---------------------------------------------------------------------------
// dtype detection for patch_coord / patch_valid (values in [0,64), 0/1)
// ---------------------------------------------------------------------------
__global__ void detect_kernel(const void* coordp, const void* validp) {
    __shared__ unsigned int s_or_all, s_or_odd, s_vb_or, s_vb_gt1;
    int tid = threadIdx.x;
    if (tid == 0) { s_or_all = 0; s_or_odd = 0; s_vb_or = 0; s_vb_gt1 = 0; }
    __syncthreads();

    const unsigned int* cw = (const unsigned int*)coordp;
    unsigned int oa = 0, oo = 0;
    for (int i = tid; i < 2048; i += 256) {
        unsigned int w = cw[i];
        oa |= w;
        if (i & 1) oo |= w;
    }
    atomicOr(&s_or_all, oa);
    atomicOr(&s_or_odd, oo);

    const unsigned char* vb = (const unsigned char*)validp;
    unsigned int vo = 0, vg = 0;
    for (int i = tid; i < 4096; i += 256) {
        unsigned char b = vb[i];
        if (i & 3) vo |= b;
        if (b > 1) vg = 1;
    }
    atomicOr(&s_vb_or, vo);
    atomicOr(&s_vb_gt1, vg);
    __syncthreads();

    if (tid == 0) {
        g_coord_fmt = (s_or_all >= 0x10000u) ? 2 : (s_or_odd == 0 ? 1 : 0);
        g_valid_fmt = s_vb_gt1 ? 2 : (s_vb_or == 0 ? 0 : 1);
    }
}

__global__ void norm_kernel(const void* coordp, const void* validp) {
    int i = blockIdx.x * blockDim.x + threadIdx.x;
    if (i >= MROWS) return;
    int cf = g_coord_fmt;
    int c0, c1;
    if (cf == 1) {
        const long long* c = (const long long*)coordp;
        c0 = (int)c[2LL * i]; c1 = (int)c[2LL * i + 1];
    } else if (cf == 2) {
        const float* c = (const float*)coordp;
        c0 = (int)c[2LL * i]; c1 = (int)c[2LL * i + 1];
    } else {
        const int* c = (const int*)coordp;
        c0 = c[2 * i]; c1 = c[2 * i + 1];
    }
    g_rawc0[i] = c0;
    g_rawc1[i] = c1;
    g_pid0[i] = c1 > 0 ? c1 : 0;
    g_pid1[i] = c0 > 0 ? c0 : 0;

    int vf = g_valid_fmt;
    bool v;
    if (vf == 0)      v = ((const int*)validp)[i] != 0;
    else if (vf == 2) v = ((const float*)validp)[i] != 0.0f;
    else              v = ((const unsigned char*)validp)[i] != 0;
    g_ok[i] = v ? 1 : 0;
}

// ---------------------------------------------------------------------------
// xprep: g_Xp[row][16*grp + 4*c + t] = tf32(x[row][16*grp + c + 4*t])
// (RNA-round once + within-16 k-permutation; removes all cvt and enables
//  LDS.128 fragment loads in the GEMM.)
// grid = MROWS blocks, 192 threads (one per (grp, c) pair, 48 groups x 4)
// ---------------------------------------------------------------------------
__global__ void __launch_bounds__(192) xprep_kernel(const float* __restrict__ x) {
    int row = blockIdx.x;
    int t = threadIdx.x;             // 0..191
    int grp = t >> 2, c = t & 3;
    const float* src = x + (size_t)row * DIM + grp * 16 + c;
    uint4 o;
    o.x = f2tf(src[0]);
    o.y = f2tf(src[4]);
    o.z = f2tf(src[8]);
    o.w = f2tf(src[12]);
    *reinterpret_cast<uint4*>(g_Xp + (size_t)row * DIM + grp * 16 + 4 * c) = o;
}

// ---------------------------------------------------------------------------
// prep: g_Wp[d][j'] = tf32(2*W[d][k(j(j'))]), bias[d] = -sum_k W[d][k]
// j' -> logical j: within-16 transpose; j -> k: patch permutation
//   j = ph*48 + pw*3 + c3  ->  k = c3*256 + ph*16 + pw
// ---------------------------------------------------------------------------
__global__ void prep_kernel(const float* __restrict__ W) {
    int d = blockIdx.x;
    const float* wrow = W + (size_t)d * DIM;
    __shared__ float red[256];
    float s = 0.f;
    for (int jp = threadIdx.x; jp < DIM; jp += 256) {
        int grp = jp >> 4, w16 = jp & 15;
        int c = w16 >> 2, t = w16 & 3;
        int j = grp * 16 + t * 4 + c;          // logical column
        int c3 = j % 3;
        int tt = j / 3;
        int pw = tt & 15;
        int ph = tt >> 4;
        int k = c3 * 256 + ph * 16 + pw;
        float w = wrow[k];
        s += w;
        g_Wp[(size_t)d * DIM + jp] = __uint_as_float(f2tf(2.0f * w));
    }
    red[threadIdx.x] = s;
    __syncthreads();
    for (int off = 128; off > 0; off >>= 1) {
        if (threadIdx.x < off) red[threadIdx.x] += red[threadIdx.x + off];
        __syncthreads();
    }
    if (threadIdx.x == 0) g_bias[d] = -red[0];
}

// ---------------------------------------------------------------------------
// Main fused GEMM: y = Xp @ Wp^T + bias + pos(gather), tf32 warp MMA
// grid (768/BN=6, 32768/BM=256), 256 threads, 2-stage cp.async pipeline.
// smem chunk swizzle: phys_chunk = chunk ^ ((row&1)<<2); one LDS.128 per lane
// per (row, k16-group) yields fragments for both k8 MMA steps.
// ---------------------------------------------------------------------------
__global__ void __launch_bounds__(256, 2)
gemm_kernel(const float* __restrict__ pos_table,
            float* __restrict__ out) {
    extern __shared__ float smem[];

    const int lane = threadIdx.x & 31;
    const int warp = threadIdx.x >> 5;
    const int wm = warp & 1;   // 0..1  (m, 64 rows each)
    const int wn = warp >> 1;  // 0..3  (n, 32 cols each)
    const int q = lane >> 2;   // 0..7
    const int c = lane & 3;    // 0..3
    const int parq = q & 1;

    float acc[4][4][4];
    #pragma unroll
    for (int a = 0; a < 4; a++)
        #pragma unroll
        for (int b = 0; b < 4; b++)
            #pragma unroll
            for (int k = 0; k < 4; k++) acc[a][b][k] = 0.f;

    const float* Abase = g_Xp + (size_t)(blockIdx.y * BM) * DIM;
    const float* Bbase = g_Wp + (size_t)(blockIdx.x * BN) * DIM;

    // async load of tile kt into stage: 2048 16B chunks, swizzled placement
    auto issue = [&](int kt, int stage) {
        float* As = smem + stage * STAGE_F;
        const float* Ag = Abase + kt * BK;
        const float* Bg = Bbase + kt * BK;
        #pragma unroll
        for (int i = 0; i < 4; i++) {
            int linear = threadIdx.x + i * 256;   // 0..1023
            int row = linear >> 3;
            int j = linear & 7;
            int phys = j ^ ((row & 1) << 2);
            uint32_t sa = (uint32_t)__cvta_generic_to_shared(&As[row * 32 + phys * 4]);
            cp_async16(sa, Ag + (size_t)row * DIM + j * 4);
            uint32_t sbp = (uint32_t)__cvta_generic_to_shared(&As[ASZ + row * 32 + phys * 4]);
            cp_async16(sbp, Bg + (size_t)row * DIM + j * 4);
        }
        asm volatile("cp.async.commit_group;\n");
    };

    issue(0, 0);

    // Prefetch epilogue row metadata
    int ep_p0[8], ep_p1[8];
    unsigned char ep_ok[8];
    {
        const int gm0 = blockIdx.y * BM + wm * 64;
        #pragma unroll
        for (int im = 0; im < 4; im++) {
            #pragma unroll
            for (int half = 0; half < 2; half++) {
                int r = gm0 + im * 16 + q + half * 8;
                ep_p0[im * 2 + half] = g_pid0[r];
                ep_p1[im * 2 + half] = g_pid1[r];
                ep_ok[im * 2 + half] = g_ok[r];
            }
        }
    }

    for (int kt = 0; kt < NKT; kt++) {
        int stage = kt & 1;
        if (kt + 1 < NKT) {
            issue(kt + 1, stage ^ 1);
            asm volatile("cp.async.wait_group 1;\n");
        } else {
            asm volatile("cp.async.wait_group 0;\n");
        }
        __syncthreads();

        const float* As = smem + stage * STAGE_F;
        // lane-constant shared bases (float offsets)
        const float* Als = As + (wm * 64 + q) * 32 + c * 4;
        const float* Bls = As + ASZ + (wn * 32 + q) * 32 + c * 4;

        #pragma unroll
        for (int grp = 0; grp < 2; grp++) {
            const int g = ((grp ^ parq) << 4);   // swizzled group offset (floats)
            float4 aq[4][2];
            float4 bq[4];
            #pragma unroll
            for (int im = 0; im < 4; im++) {
                aq[im][0] = *reinterpret_cast<const float4*>(Als + im * 512 + g);
                aq[im][1] = *reinterpret_cast<const float4*>(Als + im * 512 + 256 + g);
            }
            #pragma unroll
            for (int in = 0; in < 4; in++)
                bq[in] = *reinterpret_cast<const float4*>(Bls + in * 256 + g);

            // step 0: components (x, y);  step 1: components (z, w)
            #pragma unroll
            for (int im = 0; im < 4; im++)
                #pragma unroll
                for (int in = 0; in < 4; in++)
                    mma_tf32(acc[im][in],
                             __float_as_uint(aq[im][0].x), __float_as_uint(aq[im][1].x),
                             __float_as_uint(aq[im][0].y), __float_as_uint(aq[im][1].y),
                             __float_as_uint(bq[in].x),    __float_as_uint(bq[in].y));
            #pragma unroll
            for (int im = 0; im < 4; im++)
                #pragma unroll
                for (int in = 0; in < 4; in++)
                    mma_tf32(acc[im][in],
                             __float_as_uint(aq[im][0].z), __float_as_uint(aq[im][1].z),
                             __float_as_uint(aq[im][0].w), __float_as_uint(aq[im][1].w),
                             __float_as_uint(bq[in].z),    __float_as_uint(bq[in].w));
        }
        __syncthreads();
    }

    // Epilogue: + bias + pos gather, write float2
    const int gm0 = blockIdx.y * BM + wm * 64;
    const int gn0 = blockIdx.x * BN + wn * 32;

    #pragma unroll
    for (int im = 0; im < 4; im++) {
        int rbase = gm0 + im * 16 + q;
        #pragma unroll
        for (int half = 0; half < 2; half++) {
            int r = rbase + half * 8;
            int p0 = ep_p0[im * 2 + half];
            int p1 = ep_p1[im * 2 + half];
            bool v = (ep_ok[im * 2 + half] != 0);
            const float* t0 = pos_table + (size_t)p0 * DIM;
            const float* t1 = pos_table + POS_OFF + (size_t)p1 * DIM;
            float* orow = out + (size_t)r * DIM;
            #pragma unroll
            for (int in = 0; in < 4; in++) {
                int d = gn0 + in * 8 + c * 2;
                float v0 = acc[im][in][half * 2 + 0] + g_bias[d];
                float v1 = acc[im][in][half * 2 + 1] + g_bias[d + 1];
                if (v) {
                    v0 += t0[d] + t1[d];
                    v1 += t0[d + 1] + t1[d + 1];
                }
                float2 o; o.x = v0; o.y = v1;
                *reinterpret_cast<float2*>(&orow[d]) = o;
            }
        }
    }
}

// ---------------------------------------------------------------------------
// Aux outputs: position_ids (reversed raw coords) + padding mask, as float32
// ---------------------------------------------------------------------------
__global__ void aux_kernel(float* __restrict__ out_pid,
                           float* __restrict__ out_pad) {
    int i = blockIdx.x * blockDim.x + threadIdx.x;
    if (i < MROWS) {
        out_pid[2LL * i]     = (float)g_rawc1[i];
        out_pid[2LL * i + 1] = (float)g_rawc0[i];
        out_pad[i] = g_ok[i] ? 0.0f : 1.0f;
    }
}

extern "C" void kernel_launch(void* const* d_in, const int* in_sizes, int n_in,
                              void* d_out, int out_size) {
    const float* x     = (const float*)d_in[0];
    const void*  coord = d_in[1];
    const void*  valid = d_in[2];
    const float* W     = (const float*)d_in[3];
    const float* pos   = (const float*)d_in[4];
    float* out = (float*)d_out;

    cudaFuncSetAttribute(gemm_kernel,
                         cudaFuncAttributeMaxDynamicSharedMemorySize, SMEM_BYTES);

    detect_kernel<<<1, 256>>>(coord, valid);
    norm_kernel<<<(MROWS + 255) / 256, 256>>>(coord, valid);
    xprep_kernel<<<MROWS, 192>>>(x);
    prep_kernel<<<DIM, 256>>>(W);

    dim3 grid(DIM / BN, MROWS / BM);   // (6, 256)
    gemm_kernel<<<grid, 256, SMEM_BYTES>>>(pos, out);

    if ((size_t)out_size >= OUT_TOTAL) {
        aux_kernel<<<(MROWS + 255) / 256, 256>>>(
            out + OUT_Y, out + OUT_Y + OUT_PID);
    }
}

// round 12
// speedup vs baseline: 1.5244x; 1.3379x over previous
#include <cuda_runtime.h>
#include <cuda_fp16.h>
#include <cstdint>

// Problem constants
#define MROWS   32768
#define DIM     768
#define VPOS    10240
#define POS_OFF ((size_t)VPOS * DIM)

// GEMM tiling: CTA 128x128, 8 warps (2m x 4n), warp tile 64x32, 2-stage pipeline
// fp16 operands (11-bit significand == tf32 precision), fp32 accumulate.
// K pre-permuted per 32-chunk: k = 16g+8h+2c+e  ->  phys = 8c+4g+2h+e
// so one LDS.128 per lane per row yields the m16n8k16 fragment halves for BOTH
// k16 groups of the tile.
#define BM 128
#define BN 128
#define BK 32
#define A_STAGE_B (BM * 64)         // 8192 bytes (64B per row)
#define STAGE_B   (2 * A_STAGE_B)   // A + B = 16384 bytes
#define SMEM_BYTES (2 * STAGE_B)    // 32768 bytes, double buffered
#define NKT (DIM / BK)              // 24

// Output layout (flattened concat of the reference tuple, as float32)
#define OUT_Y     ((size_t)MROWS * DIM)
#define OUT_PID   ((size_t)MROWS * 2)
#define OUT_TOTAL (OUT_Y + OUT_PID + (size_t)MROWS)

// Device scratch
__device__ __half g_Xh[(size_t)MROWS * DIM];  // fp16, k-permuted x (48 MB)
__device__ __half g_Wh[DIM * DIM];  // patch-permuted, x2, fp16, k-permuted W
__device__ float g_bias[DIM];       // -sum_k W[d,k]
__device__ int g_pid0[MROWS];
__device__ int g_pid1[MROWS];
__device__ int g_rawc0[MROWS];
__device__ int g_rawc1[MROWS];
__device__ unsigned char g_ok[MROWS];
__device__ int g_coord_fmt;
__device__ int g_valid_fmt;

__device__ __forceinline__ void cp_async16(uint32_t s, const void* g) {
    asm volatile("cp.async.cg.shared.global [%0], [%1], 16;\n" :: "r"(s), "l"(g));
}

__device__ __forceinline__ void mma_fp16(float* c,
                                         uint32_t a0, uint32_t a1, uint32_t a2, uint32_t a3,
                                         uint32_t b0, uint32_t b1) {
    asm volatile(
        "mma.sync.aligned.m16n8k16.row.col.f32.f16.f16.f32 "
        "{%0,%1,%2,%3}, {%4,%5,%6,%7}, {%8,%9}, {%0,%1,%2,%3};\n"
        : "+f"(c[0]), "+f"(c[1]), "+f"(c[2]), "+f"(c[3])
        : "r"(a0), "r"(a1), "r"(a2), "r"(a3), "r"(b0), "r"(b1));
}

// ---------------------------------------------------------------------------
// dtype detection for patch_coord / patch_valid (values in [0,64), 0/1)
// ---------------------------------------------------------------------------
__global__ void detect_kernel(const void* coordp, const void* validp) {
    __shared__ unsigned int s_or_all, s_or_odd, s_vb_or, s_vb_gt1;
    int tid = threadIdx.x;
    if (tid == 0) { s_or_all = 0; s_or_odd = 0; s_vb_or = 0; s_vb_gt1 = 0; }
    __syncthreads();

    const unsigned int* cw = (const unsigned int*)coordp;
    unsigned int oa = 0, oo = 0;
    for (int i = tid; i < 2048; i += 256) {
        unsigned int w = cw[i];
        oa |= w;
        if (i & 1) oo |= w;
    }
    atomicOr(&s_or_all, oa);
    atomicOr(&s_or_odd, oo);

    const unsigned char* vb = (const unsigned char*)validp;
    unsigned int vo = 0, vg = 0;
    for (int i = tid; i < 4096; i += 256) {
        unsigned char b = vb[i];
        if (i & 3) vo |= b;
        if (b > 1) vg = 1;
    }
    atomicOr(&s_vb_or, vo);
    atomicOr(&s_vb_gt1, vg);
    __syncthreads();

    if (tid == 0) {
        g_coord_fmt = (s_or_all >= 0x10000u) ? 2 : (s_or_odd == 0 ? 1 : 0);
        g_valid_fmt = s_vb_gt1 ? 2 : (s_vb_or == 0 ? 0 : 1);
    }
}

__global__ void norm_kernel(const void* coordp, const void* validp) {
    int i = blockIdx.x * blockDim.x + threadIdx.x;
    if (i >= MROWS) return;
    int cf = g_coord_fmt;
    int c0, c1;
    if (cf == 1) {
        const long long* c = (const long long*)coordp;
        c0 = (int)c[2LL * i]; c1 = (int)c[2LL * i + 1];
    } else if (cf == 2) {
        const float* c = (const float*)coordp;
        c0 = (int)c[2LL * i]; c1 = (int)c[2LL * i + 1];
    } else {
        const int* c = (const int*)coordp;
        c0 = c[2 * i]; c1 = c[2 * i + 1];
    }
    g_rawc0[i] = c0;
    g_rawc1[i] = c1;
    g_pid0[i] = c1 > 0 ? c1 : 0;
    g_pid1[i] = c0 > 0 ? c0 : 0;

    int vf = g_valid_fmt;
    bool v;
    if (vf == 0)      v = ((const int*)validp)[i] != 0;
    else if (vf == 2) v = ((const float*)validp)[i] != 0.0f;
    else              v = ((const unsigned char*)validp)[i] != 0;
    g_ok[i] = v ? 1 : 0;
}

// ---------------------------------------------------------------------------
// xprep: fp16-convert + k-permute x.
// Each thread produces one uint4 (8 halves) = phys positions [8u..8u+7] of one
// 32-chunk: fixed c = u&3 within chunk ci = u>>2; reads 4 float2 pairs
// (g,h) = (0,0),(0,1),(1,0),(1,1) at logical k = 32ci + 16g + 8h + 2c.
// total threads = MROWS * 96.
// ---------------------------------------------------------------------------
__global__ void __launch_bounds__(256) xprep_kernel(const float* __restrict__ x) {
    unsigned int idx = blockIdx.x * 256 + threadIdx.x;   // < MROWS*96
    unsigned int row = idx / 96;
    unsigned int u = idx - row * 96;
    unsigned int ci = u >> 2, c = u & 3;
    const float* src = x + (size_t)row * DIM + ci * 32 + 2 * c;
    float2 p00 = *reinterpret_cast<const float2*>(src);
    float2 p01 = *reinterpret_cast<const float2*>(src + 8);
    float2 p10 = *reinterpret_cast<const float2*>(src + 16);
    float2 p11 = *reinterpret_cast<const float2*>(src + 24);
    __half2 h00 = __floats2half2_rn(p00.x, p00.y);
    __half2 h01 = __floats2half2_rn(p01.x, p01.y);
    __half2 h10 = __floats2half2_rn(p10.x, p10.y);
    __half2 h11 = __floats2half2_rn(p11.x, p11.y);
    uint4 o;
    o.x = *reinterpret_cast<uint32_t*>(&h00);
    o.y = *reinterpret_cast<uint32_t*>(&h01);
    o.z = *reinterpret_cast<uint32_t*>(&h10);
    o.w = *reinterpret_cast<uint32_t*>(&h11);
    *reinterpret_cast<uint4*>(&g_Xh[(size_t)row * DIM + ci * 32 + 8 * c]) = o;
}

// ---------------------------------------------------------------------------
// prep: g_Wh[d][phys] = fp16(2*W[d][k_patch(j(phys))]), bias[d] = -sum_k W[d][k]
// phys -> logical j (k-permutation), then j -> k via patch permutation:
//   j = ph*48 + pw*3 + c3  ->  k = c3*256 + ph*16 + pw
// ---------------------------------------------------------------------------
__global__ void prep_kernel(const float* __restrict__ W) {
    int d = blockIdx.x;
    const float* wrow = W + (size_t)d * DIM;
    __shared__ float red[256];
    float s = 0.f;
    for (int jp = threadIdx.x; jp < DIM; jp += 256) {
        int ci = jp >> 5, p = jp & 31;
        int c = p >> 3, g = (p >> 2) & 1, h = (p >> 1) & 1, e = p & 1;
        int j = ci * 32 + 16 * g + 8 * h + 2 * c + e;  // logical column
        int c3 = j % 3;
        int tt = j / 3;
        int pw = tt & 15;
        int ph = tt >> 4;
        int k = c3 * 256 + ph * 16 + pw;
        float w = wrow[k];
        s += w;
        g_Wh[(size_t)d * DIM + jp] = __float2half_rn(2.0f * w);
    }
    red[threadIdx.x] = s;
    __syncthreads();
    for (int off = 128; off > 0; off >>= 1) {
        if (threadIdx.x < off) red[threadIdx.x] += red[threadIdx.x + off];
        __syncthreads();
    }
    if (threadIdx.x == 0) g_bias[d] = -red[0];
}

// ---------------------------------------------------------------------------
// Main fused GEMM: y = Xh @ Wh^T + bias + pos(gather), fp16 m16n8k16 warp MMA
// grid (768/BN=6, 32768/BM=256), 256 threads, 2-stage cp.async pipeline.
// smem per stage: A 128 rows x 64B, B 128 x 64B. No swizzle needed: 64B rows
// place adjacent rows in disjoint bank halves -> conflict-free LDS.128 phases.
// ---------------------------------------------------------------------------
__global__ void __launch_bounds__(256, 2)
gemm_kernel(const float* __restrict__ pos_table,
            float* __restrict__ out) {
    extern __shared__ char smem[];

    const int lane = threadIdx.x & 31;
    const int warp = threadIdx.x >> 5;
    const int wm = warp & 1;   // 0..1  (m, 64 rows each)
    const int wn = warp >> 1;  // 0..3  (n, 32 cols each)
    const int q = lane >> 2;   // 0..7
    const int c = lane & 3;    // 0..3

    float acc[4][4][4];
    #pragma unroll
    for (int a = 0; a < 4; a++)
        #pragma unroll
        for (int b = 0; b < 4; b++)
            #pragma unroll
            for (int k = 0; k < 4; k++) acc[a][b][k] = 0.f;

    const __half* Abase = g_Xh + (size_t)(blockIdx.y * BM) * DIM;
    const __half* Bbase = g_Wh + (size_t)(blockIdx.x * BN) * DIM;

    // async load of tile kt into stage: 1024 16B chunks (A 512 + B 512)
    auto issue = [&](int kt, int stage) {
        char* Ss = smem + stage * STAGE_B;
        const __half* Ag = Abase + kt * BK;
        const __half* Bg = Bbase + kt * BK;
        #pragma unroll
        for (int i = 0; i < 4; i++) {
            int linear = threadIdx.x + i * 256;   // 0..1023
            if (linear < 512) {
                int row = linear >> 2, ch = linear & 3;
                uint32_t sa = (uint32_t)__cvta_generic_to_shared(Ss + row * 64 + ch * 16);
                cp_async16(sa, Ag + (size_t)row * DIM + ch * 8);
            } else {
                int l = linear - 512;
                int row = l >> 2, ch = l & 3;
                uint32_t sbp = (uint32_t)__cvta_generic_to_shared(Ss + A_STAGE_B + row * 64 + ch * 16);
                cp_async16(sbp, Bg + (size_t)row * DIM + ch * 8);
            }
        }
        asm volatile("cp.async.commit_group;\n");
    };

    issue(0, 0);

    // Prefetch epilogue row metadata
    int ep_p0[8], ep_p1[8];
    unsigned char ep_ok[8];
    {
        const int gm0 = blockIdx.y * BM + wm * 64;
        #pragma unroll
        for (int im = 0; im < 4; im++) {
            #pragma unroll
            for (int half = 0; half < 2; half++) {
                int r = gm0 + im * 16 + q + half * 8;
                ep_p0[im * 2 + half] = g_pid0[r];
                ep_p1[im * 2 + half] = g_pid1[r];
                ep_ok[im * 2 + half] = g_ok[r];
            }
        }
    }

    for (int kt = 0; kt < NKT; kt++) {
        int stage = kt & 1;
        if (kt + 1 < NKT) {
            issue(kt + 1, stage ^ 1);
            asm volatile("cp.async.wait_group 1;\n");
        } else {
            asm volatile("cp.async.wait_group 0;\n");
        }
        __syncthreads();

        const char* Ss = smem + stage * STAGE_B;
        // lane-constant bases (byte offsets): one LDS.128 per (row) covers both groups
        const char* Als = Ss + (wm * 64 + q) * 64 + c * 16;
        const char* Bls = Ss + A_STAGE_B + (wn * 32 + q) * 64 + c * 16;

        uint4 Aq[4][2];   // [im][rsel: q / q+8]
        uint4 Bq[4];      // [in]
        #pragma unroll
        for (int im = 0; im < 4; im++) {
            Aq[im][0] = *reinterpret_cast<const uint4*>(Als + im * 1024);
            Aq[im][1] = *reinterpret_cast<const uint4*>(Als + im * 1024 + 512);
        }
        #pragma unroll
        for (int in = 0; in < 4; in++)
            Bq[in] = *reinterpret_cast<const uint4*>(Bls + in * 512);

        // group 0: (.x = k-lo pair, .y = k-hi pair)
        #pragma unroll
        for (int im = 0; im < 4; im++)
            #pragma unroll
            for (int in = 0; in < 4; in++)
                mma_fp16(acc[im][in],
                         Aq[im][0].x, Aq[im][1].x, Aq[im][0].y, Aq[im][1].y,
                         Bq[in].x, Bq[in].y);
        // group 1: (.z, .w)
        #pragma unroll
        for (int im = 0; im < 4; im++)
            #pragma unroll
            for (int in = 0; in < 4; in++)
                mma_fp16(acc[im][in],
                         Aq[im][0].z, Aq[im][1].z, Aq[im][0].w, Aq[im][1].w,
                         Bq[in].z, Bq[in].w);

        __syncthreads();
    }

    // Epilogue: + bias + pos gather, write float2
    const int gm0 = blockIdx.y * BM + wm * 64;
    const int gn0 = blockIdx.x * BN + wn * 32;

    #pragma unroll
    for (int im = 0; im < 4; im++) {
        int rbase = gm0 + im * 16 + q;
        #pragma unroll
        for (int half = 0; half < 2; half++) {
            int r = rbase + half * 8;
            int p0 = ep_p0[im * 2 + half];
            int p1 = ep_p1[im * 2 + half];
            bool v = (ep_ok[im * 2 + half] != 0);
            const float* t0 = pos_table + (size_t)p0 * DIM;
            const float* t1 = pos_table + POS_OFF + (size_t)p1 * DIM;
            float* orow = out + (size_t)r * DIM;
            #pragma unroll
            for (int in = 0; in < 4; in++) {
                int d = gn0 + in * 8 + c * 2;
                float v0 = acc[im][in][half * 2 + 0] + g_bias[d];
                float v1 = acc[im][in][half * 2 + 1] + g_bias[d + 1];
                if (v) {
                    v0 += t0[d] + t1[d];
                    v1 += t0[d + 1] + t1[d + 1];
                }
                float2 o; o.x = v0; o.y = v1;
                *reinterpret_cast<float2*>(&orow[d]) = o;
            }
        }
    }
}

// ---------------------------------------------------------------------------
// Aux outputs: position_ids (reversed raw coords) + padding mask, as float32
// ---------------------------------------------------------------------------
__global__ void aux_kernel(float* __restrict__ out_pid,
                           float* __restrict__ out_pad) {
    int i = blockIdx.x * blockDim.x + threadIdx.x;
    if (i < MROWS) {
        out_pid[2LL * i]     = (float)g_rawc1[i];
        out_pid[2LL * i + 1] = (float)g_rawc0[i];
        out_pad[i] = g_ok[i] ? 0.0f : 1.0f;
    }
}

extern "C" void kernel_launch(void* const* d_in, const int* in_sizes, int n_in,
                              void* d_out, int out_size) {
    const float* x     = (const float*)d_in[0];
    const void*  coord = d_in[1];
    const void*  valid = d_in[2];
    const float* W     = (const float*)d_in[3];
    const float* pos   = (const float*)d_in[4];
    float* out = (float*)d_out;

    cudaFuncSetAttribute(gemm_kernel,
                         cudaFuncAttributeMaxDynamicSharedMemorySize, SMEM_BYTES);

    detect_kernel<<<1, 256>>>(coord, valid);
    norm_kernel<<<(MROWS + 255) / 256, 256>>>(coord, valid);
    xprep_kernel<<<(MROWS * 96) / 256, 256>>>(x);
    prep_kernel<<<DIM, 256>>>(W);

    dim3 grid(DIM / BN, MROWS / BM);   // (6, 256)
    gemm_kernel<<<grid, 256, SMEM_BYTES>>>(pos, out);

    if ((size_t)out_size >= OUT_TOTAL) {
        aux_kernel<<<(MROWS + 255) / 256, 256>>>(
            out + OUT_Y, out + OUT_Y + OUT_PID);
    }
}

// round 13
// speedup vs baseline: 1.7527x; 1.1498x over previous
#include <cuda_runtime.h>
#include <cuda_fp16.h>
#include <cstdint>

// Problem constants
#define MROWS   32768
#define DIM     768
#define VPOS    10240
#define POS_OFF ((size_t)VPOS * DIM)

// GEMM tiling: CTA 128x128, 8 warps (2m x 4n), warp tile 64x32
// fp16 operands, fp32 accumulate. BK=64 (two 32-chunks per tile), 3-stage
// cp.async pipeline with a single __syncthreads per k-tile.
// K pre-permuted per 32-chunk: k = 16g+8h+2c+e -> phys = 8c+4g+2h+e, so one
// LDS.128 per lane per row yields m16n8k16 fragments for both k16 groups.
// Row-parity chunk swizzle within 128B rows keeps LDS.128 conflict-free.
#define BM 128
#define BN 128
#define BK 64
#define A_STAGE_B (BM * 128)        // 16384 bytes (128B per row)
#define STAGE_B   (2 * A_STAGE_B)   // A + B = 32768 bytes
#define NSTAGE 3
#define SMEM_BYTES (NSTAGE * STAGE_B)  // 98304 bytes
#define NKT (DIM / BK)              // 12

// Output layout (flattened concat of the reference tuple, as float32)
#define OUT_Y     ((size_t)MROWS * DIM)
#define OUT_PID   ((size_t)MROWS * 2)
#define OUT_TOTAL (OUT_Y + OUT_PID + (size_t)MROWS)

// Device scratch
__device__ __half g_Xh[(size_t)MROWS * DIM];  // fp16, k-permuted x (48 MB)
__device__ __half g_Wh[DIM * DIM];  // patch-permuted, x2, fp16, k-permuted W
__device__ float g_bias[DIM];       // -sum_k W[d,k]
__device__ int g_pid0[MROWS];
__device__ int g_pid1[MROWS];
__device__ int g_rawc0[MROWS];
__device__ int g_rawc1[MROWS];
__device__ unsigned char g_ok[MROWS];
__device__ int g_coord_fmt;
__device__ int g_valid_fmt;

__device__ __forceinline__ void cp_async16(uint32_t s, const void* g) {
    asm volatile("cp.async.cg.shared.global [%0], [%1], 16;\n" :: "r"(s), "l"(g));
}

__device__ __forceinline__ void mma_fp16(float* c,
                                         uint32_t a0, uint32_t a1, uint32_t a2, uint32_t a3,
                                         uint32_t b0, uint32_t b1) {
    asm volatile(
        "mma.sync.aligned.m16n8k16.row.col.f32.f16.f16.f32 "
        "{%0,%1,%2,%3}, {%4,%5,%6,%7}, {%8,%9}, {%0,%1,%2,%3};\n"
        : "+f"(c[0]), "+f"(c[1]), "+f"(c[2]), "+f"(c[3])
        : "r"(a0), "r"(a1), "r"(a2), "r"(a3), "r"(b0), "r"(b1));
}

// ---------------------------------------------------------------------------
// dtype detection for patch_coord / patch_valid (values in [0,64), 0/1)
// ---------------------------------------------------------------------------
__global__ void detect_kernel(const void* coordp, const void* validp) {
    __shared__ unsigned int s_or_all, s_or_odd, s_vb_or, s_vb_gt1;
    int tid = threadIdx.x;
    if (tid == 0) { s_or_all = 0; s_or_odd = 0; s_vb_or = 0; s_vb_gt1 = 0; }
    __syncthreads();

    const unsigned int* cw = (const unsigned int*)coordp;
    unsigned int oa = 0, oo = 0;
    for (int i = tid; i < 2048; i += 256) {
        unsigned int w = cw[i];
        oa |= w;
        if (i & 1) oo |= w;
    }
    atomicOr(&s_or_all, oa);
    atomicOr(&s_or_odd, oo);

    const unsigned char* vb = (const unsigned char*)validp;
    unsigned int vo = 0, vg = 0;
    for (int i = tid; i < 4096; i += 256) {
        unsigned char b = vb[i];
        if (i & 3) vo |= b;
        if (b > 1) vg = 1;
    }
    atomicOr(&s_vb_or, vo);
    atomicOr(&s_vb_gt1, vg);
    __syncthreads();

    if (tid == 0) {
        g_coord_fmt = (s_or_all >= 0x10000u) ? 2 : (s_or_odd == 0 ? 1 : 0);
        g_valid_fmt = s_vb_gt1 ? 2 : (s_vb_or == 0 ? 0 : 1);
    }
}

__global__ void norm_kernel(const void* coordp, const void* validp) {
    int i = blockIdx.x * blockDim.x + threadIdx.x;
    if (i >= MROWS) return;
    int cf = g_coord_fmt;
    int c0, c1;
    if (cf == 1) {
        const long long* c = (const long long*)coordp;
        c0 = (int)c[2LL * i]; c1 = (int)c[2LL * i + 1];
    } else if (cf == 2) {
        const float* c = (const float*)coordp;
        c0 = (int)c[2LL * i]; c1 = (int)c[2LL * i + 1];
    } else {
        const int* c = (const int*)coordp;
        c0 = c[2 * i]; c1 = c[2 * i + 1];
    }
    g_rawc0[i] = c0;
    g_rawc1[i] = c1;
    g_pid0[i] = c1 > 0 ? c1 : 0;
    g_pid1[i] = c0 > 0 ? c0 : 0;

    int vf = g_valid_fmt;
    bool v;
    if (vf == 0)      v = ((const int*)validp)[i] != 0;
    else if (vf == 2) v = ((const float*)validp)[i] != 0.0f;
    else              v = ((const unsigned char*)validp)[i] != 0;
    g_ok[i] = v ? 1 : 0;
}

// ---------------------------------------------------------------------------
// xprep: fp16-convert + k-permute x (per 32-chunk: k=16g+8h+2c+e -> 8c+4g+2h+e)
// ---------------------------------------------------------------------------
__global__ void __launch_bounds__(256) xprep_kernel(const float* __restrict__ x) {
    unsigned int idx = blockIdx.x * 256 + threadIdx.x;   // < MROWS*96
    unsigned int row = idx / 96;
    unsigned int u = idx - row * 96;
    unsigned int ci = u >> 2, c = u & 3;
    const float* src = x + (size_t)row * DIM + ci * 32 + 2 * c;
    float2 p00 = *reinterpret_cast<const float2*>(src);
    float2 p01 = *reinterpret_cast<const float2*>(src + 8);
    float2 p10 = *reinterpret_cast<const float2*>(src + 16);
    float2 p11 = *reinterpret_cast<const float2*>(src + 24);
    __half2 h00 = __floats2half2_rn(p00.x, p00.y);
    __half2 h01 = __floats2half2_rn(p01.x, p01.y);
    __half2 h10 = __floats2half2_rn(p10.x, p10.y);
    __half2 h11 = __floats2half2_rn(p11.x, p11.y);
    uint4 o;
    o.x = *reinterpret_cast<uint32_t*>(&h00);
    o.y = *reinterpret_cast<uint32_t*>(&h01);
    o.z = *reinterpret_cast<uint32_t*>(&h10);
    o.w = *reinterpret_cast<uint32_t*>(&h11);
    *reinterpret_cast<uint4*>(&g_Xh[(size_t)row * DIM + ci * 32 + 8 * c]) = o;
}

// ---------------------------------------------------------------------------
// prep: g_Wh[d][phys] = fp16(2*W[d][k_patch(j(phys))]), bias[d] = -sum_k W[d][k]
// ---------------------------------------------------------------------------
__global__ void prep_kernel(const float* __restrict__ W) {
    int d = blockIdx.x;
    const float* wrow = W + (size_t)d * DIM;
    __shared__ float red[256];
    float s = 0.f;
    for (int jp = threadIdx.x; jp < DIM; jp += 256) {
        int ci = jp >> 5, p = jp & 31;
        int c = p >> 3, g = (p >> 2) & 1, h = (p >> 1) & 1, e = p & 1;
        int j = ci * 32 + 16 * g + 8 * h + 2 * c + e;  // logical column
        int c3 = j % 3;
        int tt = j / 3;
        int pw = tt & 15;
        int ph = tt >> 4;
        int k = c3 * 256 + ph * 16 + pw;
        float w = wrow[k];
        s += w;
        g_Wh[(size_t)d * DIM + jp] = __float2half_rn(2.0f * w);
    }
    red[threadIdx.x] = s;
    __syncthreads();
    for (int off = 128; off > 0; off >>= 1) {
        if (threadIdx.x < off) red[threadIdx.x] += red[threadIdx.x + off];
        __syncthreads();
    }
    if (threadIdx.x == 0) g_bias[d] = -red[0];
}

// ---------------------------------------------------------------------------
// Main fused GEMM: y = Xh @ Wh^T + bias + pos(gather), fp16 m16n8k16 warp MMA
// grid (768/BN=6, 32768/BM=256), 256 threads, 3-stage pipeline, 1 sync/tile.
// smem row = 128B (two 64B 32-chunks); chunk swizzle: phys = ci ^ (row&1).
// ---------------------------------------------------------------------------
__global__ void __launch_bounds__(256, 2)
gemm_kernel(const float* __restrict__ pos_table,
            float* __restrict__ out) {
    extern __shared__ char smem[];

    const int lane = threadIdx.x & 31;
    const int warp = threadIdx.x >> 5;
    const int wm = warp & 1;   // 0..1  (m, 64 rows each)
    const int wn = warp >> 1;  // 0..3  (n, 32 cols each)
    const int q = lane >> 2;   // 0..7
    const int c = lane & 3;    // 0..3
    const int parq = q & 1;

    float acc[4][4][4];
    #pragma unroll
    for (int a = 0; a < 4; a++)
        #pragma unroll
        for (int b = 0; b < 4; b++)
            #pragma unroll
            for (int k = 0; k < 4; k++) acc[a][b][k] = 0.f;

    const __half* Abase = g_Xh + (size_t)(blockIdx.y * BM) * DIM;
    const __half* Bbase = g_Wh + (size_t)(blockIdx.x * BN) * DIM;

    // async load of tile kt into stage slot: per matrix 128 rows x 8 16B-chunks
    auto issue = [&](int kt, int slot) {
        char* Ss = smem + slot * STAGE_B;
        const __half* Ag = Abase + kt * BK;
        const __half* Bg = Bbase + kt * BK;
        #pragma unroll
        for (int i = 0; i < 8; i++) {
            int linear = threadIdx.x + i * 256;   // 0..2047
            int isB = linear >> 10;               // 0: A, 1: B
            int l = linear & 1023;
            int row = l >> 3, j = l & 7;
            int phys = ((j >> 2) ^ (row & 1)) * 64 + (j & 3) * 16;
            uint32_t s = (uint32_t)__cvta_generic_to_shared(Ss + isB * A_STAGE_B + row * 128 + phys);
            const __half* g = (isB ? Bg : Ag) + (size_t)row * DIM + j * 8;
            cp_async16(s, g);
        }
        asm volatile("cp.async.commit_group;\n");
    };

    issue(0, 0);
    issue(1, 1);

    // Prefetch epilogue row metadata
    int ep_p0[8], ep_p1[8];
    unsigned char ep_ok[8];
    {
        const int gm0 = blockIdx.y * BM + wm * 64;
        #pragma unroll
        for (int im = 0; im < 4; im++) {
            #pragma unroll
            for (int half = 0; half < 2; half++) {
                int r = gm0 + im * 16 + q + half * 8;
                ep_p0[im * 2 + half] = g_pid0[r];
                ep_p1[im * 2 + half] = g_pid1[r];
                ep_ok[im * 2 + half] = g_ok[r];
            }
        }
    }

    for (int kt = 0; kt < NKT; kt++) {
        const int slot = kt % NSTAGE;
        if (kt + 1 < NKT) {
            asm volatile("cp.async.wait_group 1;\n");
        } else {
            asm volatile("cp.async.wait_group 0;\n");
        }
        __syncthreads();           // single barrier: kt data visible AND kt-1 readers done
        if (kt + 2 < NKT) issue(kt + 2, (kt + 2) % NSTAGE);

        const char* Ss = smem + slot * STAGE_B;
        // lane-constant bases (byte offsets); chunk swizzle handled via parq
        const char* Als = Ss + (wm * 64 + q) * 128 + c * 16;
        const char* Bls = Ss + A_STAGE_B + (wn * 32 + q) * 128 + c * 16;

        #pragma unroll
        for (int ci = 0; ci < 2; ci++) {
            const int g = ((ci ^ parq) << 6);   // swizzled 32-chunk offset (bytes)
            uint4 Aq[4][2];
            uint4 Bq[4];
            #pragma unroll
            for (int im = 0; im < 4; im++) {
                Aq[im][0] = *reinterpret_cast<const uint4*>(Als + im * 2048 + g);
                Aq[im][1] = *reinterpret_cast<const uint4*>(Als + im * 2048 + 1024 + g);
            }
            #pragma unroll
            for (int in = 0; in < 4; in++)
                Bq[in] = *reinterpret_cast<const uint4*>(Bls + in * 1024 + g);

            #pragma unroll
            for (int im = 0; im < 4; im++)
                #pragma unroll
                for (int in = 0; in < 4; in++)
                    mma_fp16(acc[im][in],
                             Aq[im][0].x, Aq[im][1].x, Aq[im][0].y, Aq[im][1].y,
                             Bq[in].x, Bq[in].y);
            #pragma unroll
            for (int im = 0; im < 4; im++)
                #pragma unroll
                for (int in = 0; in < 4; in++)
                    mma_fp16(acc[im][in],
                             Aq[im][0].z, Aq[im][1].z, Aq[im][0].w, Aq[im][1].w,
                             Bq[in].z, Bq[in].w);
        }
    }

    // Epilogue: + bias + pos gather, write float2
    const int gm0 = blockIdx.y * BM + wm * 64;
    const int gn0 = blockIdx.x * BN + wn * 32;

    #pragma unroll
    for (int im = 0; im < 4; im++) {
        int rbase = gm0 + im * 16 + q;
        #pragma unroll
        for (int half = 0; half < 2; half++) {
            int r = rbase + half * 8;
            int p0 = ep_p0[im * 2 + half];
            int p1 = ep_p1[im * 2 + half];
            bool v = (ep_ok[im * 2 + half] != 0);
            const float* t0 = pos_table + (size_t)p0 * DIM;
            const float* t1 = pos_table + POS_OFF + (size_t)p1 * DIM;
            float* orow = out + (size_t)r * DIM;
            #pragma unroll
            for (int in = 0; in < 4; in++) {
                int d = gn0 + in * 8 + c * 2;
                float v0 = acc[im][in][half * 2 + 0] + g_bias[d];
                float v1 = acc[im][in][half * 2 + 1] + g_bias[d + 1];
                if (v) {
                    v0 += t0[d] + t1[d];
                    v1 += t0[d + 1] + t1[d + 1];
                }
                float2 o; o.x = v0; o.y = v1;
                *reinterpret_cast<float2*>(&orow[d]) = o;
            }
        }
    }
}

// ---------------------------------------------------------------------------
// Aux outputs: position_ids (reversed raw coords) + padding mask, as float32
// ---------------------------------------------------------------------------
__global__ void aux_kernel(float* __restrict__ out_pid,
                           float* __restrict__ out_pad) {
    int i = blockIdx.x * blockDim.x + threadIdx.x;
    if (i < MROWS) {
        out_pid[2LL * i]     = (float)g_rawc1[i];
        out_pid[2LL * i + 1] = (float)g_rawc0[i];
        out_pad[i] = g_ok[i] ? 0.0f : 1.0f;
    }
}

extern "C" void kernel_launch(void* const* d_in, const int* in_sizes, int n_in,
                              void* d_out, int out_size) {
    const float* x     = (const float*)d_in[0];
    const void*  coord = d_in[1];
    const void*  valid = d_in[2];
    const float* W     = (const float*)d_in[3];
    const float* pos   = (const float*)d_in[4];
    float* out = (float*)d_out;

    cudaFuncSetAttribute(gemm_kernel,
                         cudaFuncAttributeMaxDynamicSharedMemorySize, SMEM_BYTES);

    detect_kernel<<<1, 256>>>(coord, valid);
    norm_kernel<<<(MROWS + 255) / 256, 256>>>(coord, valid);
    xprep_kernel<<<(MROWS * 96) / 256, 256>>>(x);
    prep_kernel<<<DIM, 256>>>(W);

    dim3 grid(DIM / BN, MROWS / BM);   // (6, 256)
    gemm_kernel<<<grid, 256, SMEM_BYTES>>>(pos, out);

    if ((size_t)out_size >= OUT_TOTAL) {
        aux_kernel<<<(MROWS + 255) / 256, 256>>>(
            out + OUT_Y, out + OUT_Y + OUT_PID);
    }
}

// round 14
// speedup vs baseline: 1.8851x; 1.0756x over previous
#include <cuda_runtime.h>
#include <cuda_fp16.h>
#include <cstdint>

// Problem constants
#define MROWS   32768
#define DIM     768
#define VPOS    10240
#define POS_OFF ((size_t)VPOS * DIM)

// GEMM tiling: CTA 128x128, 8 warps (2m x 4n), warp tile 64x32
// fp16 operands, fp32 accumulate. BK=64, 3-stage cp.async pipeline, 1 sync/tile.
// K pre-permuted per 32-chunk: k = 16g+8h+2c+e -> phys = 8c+4g+2h+e.
// Row-parity chunk swizzle within 128B rows keeps LDS.128 conflict-free.
#define BM 128
#define BN 128
#define BK 64
#define A_STAGE_B (BM * 128)        // 16384 bytes (128B per row)
#define STAGE_B   (2 * A_STAGE_B)   // A + B = 32768 bytes
#define NSTAGE 3
#define SMEM_BYTES (NSTAGE * STAGE_B)  // 98304 bytes
#define NKT (DIM / BK)              // 12

// Fused prologue block ranges
#define XPREP_BLOCKS ((MROWS * 96) / 256)   // 12288
#define PREP_BLOCKS  DIM                    // 768
#define NORM_BLOCKS  (MROWS / 256)          // 128
#define PRO_BLOCKS   (XPREP_BLOCKS + PREP_BLOCKS + NORM_BLOCKS)

// Output layout (flattened concat of the reference tuple, as float32)
#define OUT_Y     ((size_t)MROWS * DIM)
#define OUT_PID   ((size_t)MROWS * 2)
#define OUT_TOTAL (OUT_Y + OUT_PID + (size_t)MROWS)

// Device scratch
__device__ __half g_Xh[(size_t)MROWS * DIM];  // fp16, k-permuted x (48 MB)
__device__ __half g_Wh[DIM * DIM];  // patch-permuted, x2, fp16, k-permuted W
__device__ float g_bias[DIM];       // -sum_k W[d,k]
__device__ int g_pid0[MROWS];
__device__ int g_pid1[MROWS];
__device__ unsigned char g_ok[MROWS];

__device__ __forceinline__ void cp_async16(uint32_t s, const void* g) {
    asm volatile("cp.async.cg.shared.global [%0], [%1], 16;\n" :: "r"(s), "l"(g));
}

__device__ __forceinline__ void mma_fp16(float* c,
                                         uint32_t a0, uint32_t a1, uint32_t a2, uint32_t a3,
                                         uint32_t b0, uint32_t b1) {
    asm volatile(
        "mma.sync.aligned.m16n8k16.row.col.f32.f16.f16.f32 "
        "{%0,%1,%2,%3}, {%4,%5,%6,%7}, {%8,%9}, {%0,%1,%2,%3};\n"
        : "+f"(c[0]), "+f"(c[1]), "+f"(c[2]), "+f"(c[3])
        : "r"(a0), "r"(a1), "r"(a2), "r"(a3), "r"(b0), "r"(b1));
}

// ---------------------------------------------------------------------------
// Fused prologue: one launch, three independent block ranges.
//   [0, XPREP_BLOCKS)                : fp16-convert + k-permute x
//   [XPREP_BLOCKS, +PREP_BLOCKS)     : weight permute/scale/round + bias
//   [XPREP+PREP, +NORM_BLOCKS)       : self-detecting coord/valid normalize + aux out
// ---------------------------------------------------------------------------
__global__ void __launch_bounds__(256) prologue_kernel(
    const float* __restrict__ x,
    const float* __restrict__ W,
    const void*  coordp,
    const void*  validp,
    float* __restrict__ out_pid,
    float* __restrict__ out_pad,
    int do_aux)
{
    const int bid = blockIdx.x;
    const int tid = threadIdx.x;

    if (bid < XPREP_BLOCKS) {
        // ---- xprep: per 32-chunk k=16g+8h+2c+e -> phys=8c+4g+2h+e ----
        unsigned int idx = bid * 256 + tid;              // < MROWS*96
        unsigned int row = idx / 96;
        unsigned int u = idx - row * 96;
        unsigned int ci = u >> 2, c = u & 3;
        const float* src = x + (size_t)row * DIM + ci * 32 + 2 * c;
        float2 p00 = *reinterpret_cast<const float2*>(src);
        float2 p01 = *reinterpret_cast<const float2*>(src + 8);
        float2 p10 = *reinterpret_cast<const float2*>(src + 16);
        float2 p11 = *reinterpret_cast<const float2*>(src + 24);
        __half2 h00 = __floats2half2_rn(p00.x, p00.y);
        __half2 h01 = __floats2half2_rn(p01.x, p01.y);
        __half2 h10 = __floats2half2_rn(p10.x, p10.y);
        __half2 h11 = __floats2half2_rn(p11.x, p11.y);
        uint4 o;
        o.x = *reinterpret_cast<uint32_t*>(&h00);
        o.y = *reinterpret_cast<uint32_t*>(&h01);
        o.z = *reinterpret_cast<uint32_t*>(&h10);
        o.w = *reinterpret_cast<uint32_t*>(&h11);
        *reinterpret_cast<uint4*>(&g_Xh[(size_t)row * DIM + ci * 32 + 8 * c]) = o;
        return;
    }

    if (bid < XPREP_BLOCKS + PREP_BLOCKS) {
        // ---- prep: weights ----
        int d = bid - XPREP_BLOCKS;
        const float* wrow = W + (size_t)d * DIM;
        __shared__ float red[256];
        float s = 0.f;
        for (int jp = tid; jp < DIM; jp += 256) {
            int ci = jp >> 5, p = jp & 31;
            int c = p >> 3, g = (p >> 2) & 1, h = (p >> 1) & 1, e = p & 1;
            int j = ci * 32 + 16 * g + 8 * h + 2 * c + e;  // logical column
            int c3 = j % 3;
            int tt = j / 3;
            int pw = tt & 15;
            int ph = tt >> 4;
            int k = c3 * 256 + ph * 16 + pw;
            float w = wrow[k];
            s += w;
            g_Wh[(size_t)d * DIM + jp] = __float2half_rn(2.0f * w);
        }
        red[tid] = s;
        __syncthreads();
        for (int off = 128; off > 0; off >>= 1) {
            if (tid < off) red[tid] += red[tid + off];
            __syncthreads();
        }
        if (tid == 0) g_bias[d] = -red[0];
        return;
    }

    // ---- norm (+self-detect) + aux ----
    {
        __shared__ unsigned int s_or_all, s_or_odd, s_vb_or, s_vb_gt1;
        __shared__ int sh_cf, sh_vf;
        if (tid == 0) { s_or_all = 0; s_or_odd = 0; s_vb_or = 0; s_vb_gt1 = 0; }
        __syncthreads();

        const unsigned int* cw = (const unsigned int*)coordp;
        unsigned int oa = 0, oo = 0;
        for (int i = tid; i < 2048; i += 256) {          // first 8KB (buffer >= 256KB)
            unsigned int w = cw[i];
            oa |= w;
            if (i & 1) oo |= w;
        }
        atomicOr(&s_or_all, oa);
        atomicOr(&s_or_odd, oo);

        const unsigned char* vb = (const unsigned char*)validp;
        unsigned int vo = 0, vg = 0;
        for (int i = tid; i < 4096; i += 256) {          // first 4KB (buffer >= 32KB)
            unsigned char b = vb[i];
            if (i & 3) vo |= b;
            if (b > 1) vg = 1;
        }
        atomicOr(&s_vb_or, vo);
        atomicOr(&s_vb_gt1, vg);
        __syncthreads();

        if (tid == 0) {
            sh_cf = (s_or_all >= 0x10000u) ? 2 : (s_or_odd == 0 ? 1 : 0);
            sh_vf = s_vb_gt1 ? 2 : (s_vb_or == 0 ? 0 : 1);
        }
        __syncthreads();
        int cf = sh_cf, vf = sh_vf;

        int i = (bid - XPREP_BLOCKS - PREP_BLOCKS) * 256 + tid;   // < MROWS
        int c0, c1;
        if (cf == 1) {
            const long long* c = (const long long*)coordp;
            c0 = (int)c[2LL * i]; c1 = (int)c[2LL * i + 1];
        } else if (cf == 2) {
            const float* c = (const float*)coordp;
            c0 = (int)c[2LL * i]; c1 = (int)c[2LL * i + 1];
        } else {
            const int* c = (const int*)coordp;
            c0 = c[2 * i]; c1 = c[2 * i + 1];
        }
        g_pid0[i] = c1 > 0 ? c1 : 0;
        g_pid1[i] = c0 > 0 ? c0 : 0;

        bool v;
        if (vf == 0)      v = ((const int*)validp)[i] != 0;
        else if (vf == 2) v = ((const float*)validp)[i] != 0.0f;
        else              v = ((const unsigned char*)validp)[i] != 0;
        g_ok[i] = v ? 1 : 0;

        if (do_aux) {
            out_pid[2LL * i]     = (float)c1;
            out_pid[2LL * i + 1] = (float)c0;
            out_pad[i] = v ? 0.0f : 1.0f;
        }
    }
}

// ---------------------------------------------------------------------------
// Main fused GEMM: y = Xh @ Wh^T + bias + pos(gather), fp16 m16n8k16 warp MMA
// grid (768/BN=6, 32768/BM=256), 256 threads, 3-stage pipeline, 1 sync/tile.
// smem row = 128B (two 64B 32-chunks); chunk swizzle: phys = ci ^ (row&1).
// ---------------------------------------------------------------------------
__global__ void __launch_bounds__(256, 2)
gemm_kernel(const float* __restrict__ pos_table,
            float* __restrict__ out) {
    extern __shared__ char smem[];

    const int lane = threadIdx.x & 31;
    const int warp = threadIdx.x >> 5;
    const int wm = warp & 1;   // 0..1  (m, 64 rows each)
    const int wn = warp >> 1;  // 0..3  (n, 32 cols each)
    const int q = lane >> 2;   // 0..7
    const int c = lane & 3;    // 0..3
    const int parq = q & 1;

    float acc[4][4][4];
    #pragma unroll
    for (int a = 0; a < 4; a++)
        #pragma unroll
        for (int b = 0; b < 4; b++)
            #pragma unroll
            for (int k = 0; k < 4; k++) acc[a][b][k] = 0.f;

    const __half* Abase = g_Xh + (size_t)(blockIdx.y * BM) * DIM;
    const __half* Bbase = g_Wh + (size_t)(blockIdx.x * BN) * DIM;

    // async load of tile kt into stage slot: per matrix 128 rows x 8 16B-chunks
    auto issue = [&](int kt, int slot) {
        char* Ss = smem + slot * STAGE_B;
        const __half* Ag = Abase + kt * BK;
        const __half* Bg = Bbase + kt * BK;
        #pragma unroll
        for (int i = 0; i < 8; i++) {
            int linear = threadIdx.x + i * 256;   // 0..2047
            int isB = linear >> 10;               // 0: A, 1: B
            int l = linear & 1023;
            int row = l >> 3, j = l & 7;
            int phys = ((j >> 2) ^ (row & 1)) * 64 + (j & 3) * 16;
            uint32_t s = (uint32_t)__cvta_generic_to_shared(Ss + isB * A_STAGE_B + row * 128 + phys);
            const __half* g = (isB ? Bg : Ag) + (size_t)row * DIM + j * 8;
            cp_async16(s, g);
        }
        asm volatile("cp.async.commit_group;\n");
    };

    issue(0, 0);
    issue(1, 1);

    // Prefetch epilogue row metadata
    int ep_p0[8], ep_p1[8];
    unsigned char ep_ok[8];
    {
        const int gm0 = blockIdx.y * BM + wm * 64;
        #pragma unroll
        for (int im = 0; im < 4; im++) {
            #pragma unroll
            for (int half = 0; half < 2; half++) {
                int r = gm0 + im * 16 + q + half * 8;
                ep_p0[im * 2 + half] = g_pid0[r];
                ep_p1[im * 2 + half] = g_pid1[r];
                ep_ok[im * 2 + half] = g_ok[r];
            }
        }
    }

    for (int kt = 0; kt < NKT; kt++) {
        const int slot = kt % NSTAGE;
        if (kt + 1 < NKT) {
            asm volatile("cp.async.wait_group 1;\n");
        } else {
            asm volatile("cp.async.wait_group 0;\n");
        }
        __syncthreads();           // single barrier: kt data visible AND kt-1 readers done
        if (kt + 2 < NKT) issue(kt + 2, (kt + 2) % NSTAGE);

        const char* Ss = smem + slot * STAGE_B;
        const char* Als = Ss + (wm * 64 + q) * 128 + c * 16;
        const char* Bls = Ss + A_STAGE_B + (wn * 32 + q) * 128 + c * 16;

        #pragma unroll
        for (int ci = 0; ci < 2; ci++) {
            const int g = ((ci ^ parq) << 6);   // swizzled 32-chunk offset (bytes)
            uint4 Aq[4][2];
            uint4 Bq[4];
            #pragma unroll
            for (int im = 0; im < 4; im++) {
                Aq[im][0] = *reinterpret_cast<const uint4*>(Als + im * 2048 + g);
                Aq[im][1] = *reinterpret_cast<const uint4*>(Als + im * 2048 + 1024 + g);
            }
            #pragma unroll
            for (int in = 0; in < 4; in++)
                Bq[in] = *reinterpret_cast<const uint4*>(Bls + in * 1024 + g);

            #pragma unroll
            for (int im = 0; im < 4; im++)
                #pragma unroll
                for (int in = 0; in < 4; in++)
                    mma_fp16(acc[im][in],
                             Aq[im][0].x, Aq[im][1].x, Aq[im][0].y, Aq[im][1].y,
                             Bq[in].x, Bq[in].y);
            #pragma unroll
            for (int im = 0; im < 4; im++)
                #pragma unroll
                for (int in = 0; in < 4; in++)
                    mma_fp16(acc[im][in],
                             Aq[im][0].z, Aq[im][1].z, Aq[im][0].w, Aq[im][1].w,
                             Bq[in].z, Bq[in].w);
        }
    }

    // Epilogue: + bias + pos gather, write float2
    const int gm0 = blockIdx.y * BM + wm * 64;
    const int gn0 = blockIdx.x * BN + wn * 32;

    #pragma unroll
    for (int im = 0; im < 4; im++) {
        int rbase = gm0 + im * 16 + q;
        #pragma unroll
        for (int half = 0; half < 2; half++) {
            int r = rbase + half * 8;
            int p0 = ep_p0[im * 2 + half];
            int p1 = ep_p1[im * 2 + half];
            bool v = (ep_ok[im * 2 + half] != 0);
            const float* t0 = pos_table + (size_t)p0 * DIM;
            const float* t1 = pos_table + POS_OFF + (size_t)p1 * DIM;
            float* orow = out + (size_t)r * DIM;
            #pragma unroll
            for (int in = 0; in < 4; in++) {
                int d = gn0 + in * 8 + c * 2;
                float v0 = acc[im][in][half * 2 + 0] + g_bias[d];
                float v1 = acc[im][in][half * 2 + 1] + g_bias[d + 1];
                if (v) {
                    v0 += t0[d] + t1[d];
                    v1 += t0[d + 1] + t1[d + 1];
                }
                float2 o; o.x = v0; o.y = v1;
                *reinterpret_cast<float2*>(&orow[d]) = o;
            }
        }
    }
}

extern "C" void kernel_launch(void* const* d_in, const int* in_sizes, int n_in,
                              void* d_out, int out_size) {
    const float* x     = (const float*)d_in[0];
    const void*  coord = d_in[1];
    const void*  valid = d_in[2];
    const float* W     = (const float*)d_in[3];
    const float* pos   = (const float*)d_in[4];
    float* out = (float*)d_out;

    cudaFuncSetAttribute(gemm_kernel,
                         cudaFuncAttributeMaxDynamicSharedMemorySize, SMEM_BYTES);

    int do_aux = ((size_t)out_size >= OUT_TOTAL) ? 1 : 0;
    prologue_kernel<<<PRO_BLOCKS, 256>>>(
        x, W, coord, valid,
        out + OUT_Y, out + OUT_Y + OUT_PID, do_aux);

    dim3 grid(DIM / BN, MROWS / BM);   // (6, 256)
    gemm_kernel<<<grid, 256, SMEM_BYTES>>>(pos, out);
}